// round 4
// baseline (speedup 1.0000x reference)
#include <cuda_runtime.h>
#include <cstdint>
#include <cstddef>

// Problem constants
#define BB 32
#define TT 256
#define DD 512
#define HH 1024
#define GN 4096          // 4*H gate columns
#define MM (BB*TT)       // 8192 rows

#define NBLK 128         // persistent blocks (1/SM, all co-resident)
#define UPB 8            // hidden units per block (x4 gates = 32 cols)

// ---------------- scratch (static device allocations; no cudaMalloc) -------
__device__ float g_zx[(size_t)MM * GN];      // input-projection Z for current layer (128 MB)
__device__ float g_h1[(size_t)MM * HH];      // layer-1 hidden history (32 MB)
__device__ float g_hT[2][HH * BB];           // transposed h state double buffer [unit][batch]
__device__ unsigned g_bar_count;
__device__ unsigned g_bar_phase;

// ---------------- f32x2 packed FMA (Blackwell FFMA2) -----------------------
__device__ __forceinline__ float2 ffma2(float2 a, float2 b, float2 c) {
    unsigned long long au = *reinterpret_cast<unsigned long long*>(&a);
    unsigned long long bu = *reinterpret_cast<unsigned long long*>(&b);
    unsigned long long cu = *reinterpret_cast<unsigned long long*>(&c);
    unsigned long long du;
    asm("fma.rn.f32x2 %0, %1, %2, %3;" : "=l"(du) : "l"(au), "l"(bu), "l"(cu));
    return *reinterpret_cast<float2*>(&du);
}

// ---------------- big time-parallel GEMM: C[M,N] = A[M,K] * B[K,N] ---------
#define GM_BM 128
#define GM_BN 128
#define GM_BK 16

__global__ __launch_bounds__(256, 1) void sgemm_kernel(
    const float* __restrict__ A, const float* __restrict__ B,
    float* __restrict__ C, int M, int N, int K)
{
    __shared__ float As[GM_BK][GM_BM];
    __shared__ float Bs[GM_BK][GM_BN];

    const int tid = threadIdx.x;
    const int m0 = blockIdx.y * GM_BM;
    const int n0 = blockIdx.x * GM_BN;
    const int tx = tid & 15;
    const int ty = tid >> 4;

    float2 acc2[8][4];
#pragma unroll
    for (int i = 0; i < 8; i++)
#pragma unroll
        for (int j = 0; j < 4; j++) acc2[i][j] = make_float2(0.f, 0.f);

    for (int k0 = 0; k0 < K; k0 += GM_BK) {
#pragma unroll
        for (int l = 0; l < 2; ++l) {
            int i = tid + l * 256;
            int row = i >> 2;
            int kq = (i & 3) << 2;
            float4 v = *(const float4*)(A + (size_t)(m0 + row) * K + k0 + kq);
            As[kq + 0][row] = v.x;
            As[kq + 1][row] = v.y;
            As[kq + 2][row] = v.z;
            As[kq + 3][row] = v.w;
        }
#pragma unroll
        for (int l = 0; l < 2; ++l) {
            int i = tid + l * 256;
            int kr = i >> 5;
            int nq = (i & 31) << 2;
            *(float4*)(&Bs[kr][nq]) = *(const float4*)(B + (size_t)(k0 + kr) * N + n0 + nq);
        }
        __syncthreads();

#pragma unroll
        for (int k = 0; k < GM_BK; ++k) {
            float a[8];
            *(float4*)&a[0] = *(const float4*)&As[k][ty * 4];
            *(float4*)&a[4] = *(const float4*)&As[k][64 + ty * 4];
            float4 bv0 = *(const float4*)&Bs[k][tx * 4];
            float4 bv1 = *(const float4*)&Bs[k][64 + tx * 4];
            float2 b2[4];
            b2[0] = make_float2(bv0.x, bv0.y);
            b2[1] = make_float2(bv0.z, bv0.w);
            b2[2] = make_float2(bv1.x, bv1.y);
            b2[3] = make_float2(bv1.z, bv1.w);
#pragma unroll
            for (int i = 0; i < 8; i++) {
                float2 ad = make_float2(a[i], a[i]);
#pragma unroll
                for (int jp = 0; jp < 4; jp++)
                    acc2[i][jp] = ffma2(ad, b2[jp], acc2[i][jp]);
            }
        }
        __syncthreads();
    }

#pragma unroll
    for (int i = 0; i < 8; i++) {
        int row = m0 + ((i < 4) ? (ty * 4 + i) : (64 + ty * 4 + (i - 4)));
        float* cp = C + (size_t)row * N + n0;
        float4 v0 = make_float4(acc2[i][0].x, acc2[i][0].y, acc2[i][1].x, acc2[i][1].y);
        float4 v1 = make_float4(acc2[i][2].x, acc2[i][2].y, acc2[i][3].x, acc2[i][3].y);
        *(float4*)(cp + tx * 4) = v0;
        *(float4*)(cp + 64 + tx * 4) = v1;
    }
}

// ---------------- reset: barrier counters + h state ------------------------
__global__ void reset_kernel() {
    int i = blockIdx.x * blockDim.x + threadIdx.x;
    if (i == 0) { g_bar_count = 0; g_bar_phase = 0; }
    if (i < 2 * HH * BB) ((float*)g_hT)[i] = 0.f;
}

// ---------------- persistent LSTM layer kernel -----------------------------
// Grid: 128 blocks x 256 threads. Block bx owns units [bx*8, bx*8+8) x 4 gates.
// Weight slice (1024 x 32) cached in smem for all 256 steps.
// smem: w_s [1024*32] (128KB) | h_s [128*32] (16KB) | z_s [32*33] (4.1KB)
__global__ __launch_bounds__(256, 1) void lstm_persistent(
    const float* __restrict__ Wh,       // [HH][GN] recurrent weights
    const float* __restrict__ zx,       // [MM][GN], row = b*TT + t
    const float* __restrict__ bias,     // [GN]
    float* __restrict__ hist)           // [MM][HH] h history out
{
    extern __shared__ float smem[];
    float* w_s = smem;                   // [k*32 + c]
    float* h_s = smem + HH * 32;         // [kk*32 + b]
    float* z_s = smem + HH * 32 + 128 * 32;  // [c*33 + b]

    const int tid = threadIdx.x;
    const int u0 = blockIdx.x * UPB;
    const int c = tid & 31;              // local col: gate = c>>3, unit = c&7
    const int bq = tid >> 5;             // batch quad 0..7
    const int gu = tid & 7;              // gate-phase unit
    const int gb = tid >> 3;             // gate-phase batch

    float* hT = (float*)g_hT;

    // ---- load weight slice into smem (once) ----
#pragma unroll 4
    for (int l = 0; l < 128; ++l) {
        int i = tid + l * 256;           // 0..32767
        int k = i >> 5;
        int cc = i & 31;
        int col = ((cc >> 3) << 10) + u0 + (cc & 7);
        w_s[i] = Wh[(size_t)k * GN + col];
    }

    // gate-phase per-thread bias
    float bi = bias[0 * HH + u0 + gu];
    float bj = bias[1 * HH + u0 + gu];
    float bf = bias[2 * HH + u0 + gu];
    float bo = bias[3 * HH + u0 + gu];

    float c_reg = 0.f;
    __syncthreads();

    for (int t = 0; t < TT; ++t) {
        const float* hread = hT + (t & 1) * (HH * BB);
        float* hwrite = hT + ((t + 1) & 1) * (HH * BB);

        // prefetch this step's zx for the gate phase (consumed ~8000 cyc later)
        const float* zxr = zx + (size_t)(gb * TT + t) * GN + u0 + gu;
        float zxi = __ldg(zxr);
        float zxj = __ldg(zxr + HH);
        float zxf = __ldg(zxr + 2 * HH);
        float zxo = __ldg(zxr + 3 * HH);

        float2 acc0 = make_float2(0.f, 0.f);
        float2 acc1 = make_float2(0.f, 0.f);

#pragma unroll 1
        for (int ch = 0; ch < 8; ++ch) {
            int k0 = ch << 7;  // *128
            // cooperative load of h chunk [128 k][32 b]: 1024 float4s, 4/thread
#pragma unroll
            for (int l = 0; l < 4; ++l) {
                int i = tid + l * 256;       // 0..1023 float4s
                int row = i >> 3;            // 0..127
                int c4 = (i & 7) << 2;       // 0,4,..28
                float4 v = __ldcg((const float4*)(hread + (k0 + row) * BB + c4));
                *(float4*)(h_s + row * 32 + c4) = v;
            }
            __syncthreads();
#pragma unroll 8
            for (int kk = 0; kk < 128; ++kk) {
                float4 hv = *(const float4*)(h_s + kk * 32 + bq * 4);
                float w = w_s[(k0 + kk) * 32 + c];
                float2 wd = make_float2(w, w);
                acc0 = ffma2(make_float2(hv.x, hv.y), wd, acc0);
                acc1 = ffma2(make_float2(hv.z, hv.w), wd, acc1);
            }
            __syncthreads();
        }

        // stage z to smem for gate-phase remap
        z_s[c * 33 + bq * 4 + 0] = acc0.x;
        z_s[c * 33 + bq * 4 + 1] = acc0.y;
        z_s[c * 33 + bq * 4 + 2] = acc1.x;
        z_s[c * 33 + bq * 4 + 3] = acc1.y;
        __syncthreads();

        // ---- gate phase: thread = (unit gu, batch gb) ----
        float zi = z_s[(0 * 8 + gu) * 33 + gb] + zxi + bi;
        float zj = z_s[(1 * 8 + gu) * 33 + gb] + zxj + bj;
        float zf = z_s[(2 * 8 + gu) * 33 + gb] + zxf + bf;
        float zo = z_s[(3 * 8 + gu) * 33 + gb] + zxo + bo;

        float ig = 1.f / (1.f + expf(-zi));
        float fg = 1.f / (1.f + expf(-(zf + 1.0f)));   // forget bias 1.0
        float jt = tanhf(zj);
        float cn = fg * c_reg + ig * jt;
        float og = 1.f / (1.f + expf(-zo));
        float hn = og * tanhf(cn);
        c_reg = cn;

        hwrite[(u0 + gu) * BB + gb] = hn;
        hist[(size_t)(gb * TT + t) * HH + u0 + gu] = hn;

        __syncthreads();   // z_s reuse guard + all gate writes issued

        // ---- grid barrier (skip after final step) ----
        if (t < TT - 1) {
            if (tid == 0) {
                __threadfence();
                unsigned prev = atomicAdd(&g_bar_count, 1u);
                unsigned target = (unsigned)(t + 1);
                if (prev == NBLK - 1) {
                    atomicExch(&g_bar_count, 0u);
                    atomicAdd(&g_bar_phase, 1u);   // release
                } else {
                    while (atomicAdd(&g_bar_phase, 0u) < target) __nanosleep(64);
                }
                __threadfence();
            }
            __syncthreads();
        }
    }
}

// ---------------- host orchestration ---------------------------------------
extern "C" void kernel_launch(void* const* d_in, const int* in_sizes, int n_in,
                              void* d_out, int out_size)
{
    const float *x = nullptr, *W1 = nullptr, *b1 = nullptr, *W2 = nullptr, *b2 = nullptr;
    for (int i = 0; i < n_in; i++) {
        int s = in_sizes[i];
        const float* p = (const float*)d_in[i];
        if (s == BB * TT * DD) x = p;
        else if (s == (DD + HH) * GN) W1 = p;
        else if (s == (HH + HH) * GN) W2 = p;
        else if (s == GN) { if (!b1) b1 = p; else b2 = p; }
    }
    float* out = (float*)d_out;

    float *zx, *h1;
    { void* p; cudaGetSymbolAddress(&p, g_zx); zx = (float*)p; }
    { void* p; cudaGetSymbolAddress(&p, g_h1); h1 = (float*)p; }

    const int SMEM_BYTES = (HH * 32 + 128 * 32 + 32 * 33) * 4;  // ~151.7 KB
    cudaFuncSetAttribute(lstm_persistent,
                         cudaFuncAttributeMaxDynamicSharedMemorySize, SMEM_BYTES);

    dim3 gemm_grid(GN / GM_BN, MM / GM_BM);   // (32, 64)

    // ---- Layer 1 ----
    sgemm_kernel<<<gemm_grid, 256>>>(x, W1, zx, MM, GN, DD);
    reset_kernel<<<(2 * HH * BB + 255) / 256, 256>>>();
    lstm_persistent<<<NBLK, 256, SMEM_BYTES>>>(W1 + (size_t)DD * GN, zx, b1, h1);

    // ---- Layer 2 ----
    sgemm_kernel<<<gemm_grid, 256>>>(h1, W2, zx, MM, GN, HH);
    reset_kernel<<<(2 * HH * BB + 255) / 256, 256>>>();
    lstm_persistent<<<NBLK, 256, SMEM_BYTES>>>(W2 + (size_t)HH * GN, zx, b2, out);
}

// round 5
// speedup vs baseline: 1.1491x; 1.1491x over previous
#include <cuda_runtime.h>
#include <cstdint>
#include <cstddef>

// Problem constants
#define BB 32
#define TT 256
#define DD 512
#define HH 1024
#define GN 4096          // 4*H gate columns
#define MM (BB*TT)       // 8192 rows

#define NBLK 128         // persistent blocks (1/SM, all co-resident)
#define UPB 8            // hidden units per block (x4 gates = 32 cols)
#define PTH 128          // threads in persistent kernel

// ---------------- scratch (static device allocations; no cudaMalloc) -------
__device__ float g_zx[(size_t)MM * GN];      // input-projection Z for current layer (128 MB)
__device__ float g_h1[(size_t)MM * HH];      // layer-1 hidden history (32 MB)
__device__ float g_hT[2][HH * BB];           // transposed h state double buffer [unit][batch]
__device__ unsigned g_bar_count;
__device__ unsigned g_bar_phase;

// ---------------- f32x2 packed FMA (Blackwell FFMA2) -----------------------
__device__ __forceinline__ float2 ffma2(float2 a, float2 b, float2 c) {
    unsigned long long au = *reinterpret_cast<unsigned long long*>(&a);
    unsigned long long bu = *reinterpret_cast<unsigned long long*>(&b);
    unsigned long long cu = *reinterpret_cast<unsigned long long*>(&c);
    unsigned long long du;
    asm("fma.rn.f32x2 %0, %1, %2, %3;" : "=l"(du) : "l"(au), "l"(bu), "l"(cu));
    return *reinterpret_cast<float2*>(&du);
}

// ---------------- big time-parallel GEMM: C[M,N] = A[M,K] * B[K,N] ---------
#define GM_BM 128
#define GM_BN 128
#define GM_BK 16

__global__ __launch_bounds__(256, 2) void sgemm_kernel(
    const float* __restrict__ A, const float* __restrict__ B,
    float* __restrict__ C, int M, int N, int K)
{
    __shared__ float As[GM_BK][GM_BM];
    __shared__ float Bs[GM_BK][GM_BN];

    const int tid = threadIdx.x;
    const int m0 = blockIdx.y * GM_BM;
    const int n0 = blockIdx.x * GM_BN;
    const int tx = tid & 15;
    const int ty = tid >> 4;

    float2 acc2[8][4];
#pragma unroll
    for (int i = 0; i < 8; i++)
#pragma unroll
        for (int j = 0; j < 4; j++) acc2[i][j] = make_float2(0.f, 0.f);

    for (int k0 = 0; k0 < K; k0 += GM_BK) {
#pragma unroll
        for (int l = 0; l < 2; ++l) {
            int i = tid + l * 256;
            int row = i >> 2;
            int kq = (i & 3) << 2;
            float4 v = *(const float4*)(A + (size_t)(m0 + row) * K + k0 + kq);
            As[kq + 0][row] = v.x;
            As[kq + 1][row] = v.y;
            As[kq + 2][row] = v.z;
            As[kq + 3][row] = v.w;
        }
#pragma unroll
        for (int l = 0; l < 2; ++l) {
            int i = tid + l * 256;
            int kr = i >> 5;
            int nq = (i & 31) << 2;
            *(float4*)(&Bs[kr][nq]) = *(const float4*)(B + (size_t)(k0 + kr) * N + n0 + nq);
        }
        __syncthreads();

#pragma unroll
        for (int k = 0; k < GM_BK; ++k) {
            float a[8];
            *(float4*)&a[0] = *(const float4*)&As[k][ty * 4];
            *(float4*)&a[4] = *(const float4*)&As[k][64 + ty * 4];
            float4 bv0 = *(const float4*)&Bs[k][tx * 4];
            float4 bv1 = *(const float4*)&Bs[k][64 + tx * 4];
            float2 b2[4];
            b2[0] = make_float2(bv0.x, bv0.y);
            b2[1] = make_float2(bv0.z, bv0.w);
            b2[2] = make_float2(bv1.x, bv1.y);
            b2[3] = make_float2(bv1.z, bv1.w);
#pragma unroll
            for (int i = 0; i < 8; i++) {
                float2 ad = make_float2(a[i], a[i]);
#pragma unroll
                for (int jp = 0; jp < 4; jp++)
                    acc2[i][jp] = ffma2(ad, b2[jp], acc2[i][jp]);
            }
        }
        __syncthreads();
    }

#pragma unroll
    for (int i = 0; i < 8; i++) {
        int row = m0 + ((i < 4) ? (ty * 4 + i) : (64 + ty * 4 + (i - 4)));
        float* cp = C + (size_t)row * N + n0;
        float4 v0 = make_float4(acc2[i][0].x, acc2[i][0].y, acc2[i][1].x, acc2[i][1].y);
        float4 v1 = make_float4(acc2[i][2].x, acc2[i][2].y, acc2[i][3].x, acc2[i][3].y);
        *(float4*)(cp + tx * 4) = v0;
        *(float4*)(cp + 64 + tx * 4) = v1;
    }
}

// ---------------- reset: barrier counters + h state ------------------------
__global__ void reset_kernel() {
    int i = blockIdx.x * blockDim.x + threadIdx.x;
    if (i == 0) { g_bar_count = 0; g_bar_phase = 0; }
    if (i < 2 * HH * BB) ((float*)g_hT)[i] = 0.f;
}

// ---------------- persistent LSTM layer kernel -----------------------------
// Grid: 128 blocks x 128 threads. Block bx owns units [bx*8, bx*8+8) x 4 gates
// (32 cols). Weight slice (1024 x 32) cached in smem for all 256 steps.
// Thread (cp, bq): cols {2cp, 2cp+1}, batches {4bq..4bq+3} -> 8 accumulators.
// Per kk: 1 LDS.128 (h, broadcast) + 1 LDS.64 (w pair) feeding 4 FFMA2.
// smem: w_s [1024*32] (128KB) | h_s [128*32] (16KB) | z_s [32*36] (4.5KB)
__global__ __launch_bounds__(PTH, 1) void lstm_persistent(
    const float* __restrict__ Wh,       // [HH][GN] recurrent weights
    const float* __restrict__ zx,       // [MM][GN], row = b*TT + t
    const float* __restrict__ bias,     // [GN]
    float* __restrict__ hist)           // [MM][HH] h history out
{
    extern __shared__ float smem[];
    float* w_s = smem;                        // [k*32 + c]
    float* h_s = smem + HH * 32;              // [kk*32 + b]
    float* z_s = smem + HH * 32 + 128 * 32;   // [c*36 + b]

    const int tid = threadIdx.x;
    const int u0 = blockIdx.x * UPB;
    const int cp = tid & 15;             // col pair: cols {2cp, 2cp+1}
    const int bq = tid >> 4;             // batch quad 0..7
    const int gu = tid & 7;              // gate-phase unit
    const int gb = tid >> 3;             // gate-phase batch (and gb+16)

    float* hT = (float*)g_hT;

    // ---- load weight slice into smem (once) ----
#pragma unroll 8
    for (int l = 0; l < 256; ++l) {
        int i = tid + l * PTH;           // 0..32767
        int k = i >> 5;
        int cc = i & 31;
        int col = ((cc >> 3) << 10) + u0 + (cc & 7);
        w_s[i] = Wh[(size_t)k * GN + col];
    }

    // gate-phase per-thread bias (same unit for both batches)
    float bi = bias[0 * HH + u0 + gu];
    float bj = bias[1 * HH + u0 + gu];
    float bf = bias[2 * HH + u0 + gu];
    float bo = bias[3 * HH + u0 + gu];

    float creg[2] = {0.f, 0.f};
    __syncthreads();

    for (int t = 0; t < TT; ++t) {
        const float* hread = hT + (t & 1) * (HH * BB);
        float* hwrite = hT + ((t + 1) & 1) * (HH * BB);

        // prefetch this step's zx for the gate phase (consumed ~8000 cyc later)
        float zxi[2], zxj[2], zxf[2], zxo[2];
#pragma unroll
        for (int rb = 0; rb < 2; ++rb) {
            int b = gb + rb * 16;
            const float* zxr = zx + (size_t)(b * TT + t) * GN + u0 + gu;
            zxi[rb] = __ldg(zxr);
            zxj[rb] = __ldg(zxr + HH);
            zxf[rb] = __ldg(zxr + 2 * HH);
            zxo[rb] = __ldg(zxr + 3 * HH);
        }

        float2 a00 = make_float2(0.f, 0.f);  // col0, batches lo
        float2 a01 = make_float2(0.f, 0.f);  // col0, batches hi
        float2 a10 = make_float2(0.f, 0.f);  // col1, batches lo
        float2 a11 = make_float2(0.f, 0.f);  // col1, batches hi

#pragma unroll 1
        for (int ch = 0; ch < 8; ++ch) {
            int k0 = ch << 7;  // *128
            // cooperative load of h chunk [128 k][32 b]: 1024 float4s, 8/thread
#pragma unroll
            for (int l = 0; l < 8; ++l) {
                int i = tid + l * PTH;       // 0..1023 float4s
                int row = i >> 3;            // 0..127
                int c4 = (i & 7) << 2;       // 0,4,..28
                float4 v = __ldcg((const float4*)(hread + (k0 + row) * BB + c4));
                *(float4*)(h_s + row * 32 + c4) = v;
            }
            __syncthreads();
#pragma unroll 8
            for (int kk = 0; kk < 128; ++kk) {
                float4 hv = *(const float4*)(h_s + kk * 32 + bq * 4);
                float2 w2 = *(const float2*)(w_s + (k0 + kk) * 32 + cp * 2);
                float2 hlo = make_float2(hv.x, hv.y);
                float2 hhi = make_float2(hv.z, hv.w);
                float2 w0 = make_float2(w2.x, w2.x);
                float2 w1 = make_float2(w2.y, w2.y);
                a00 = ffma2(hlo, w0, a00);
                a01 = ffma2(hhi, w0, a01);
                a10 = ffma2(hlo, w1, a10);
                a11 = ffma2(hhi, w1, a11);
            }
            __syncthreads();
        }

        // stage z to smem for gate-phase remap
        *(float4*)(z_s + (2 * cp + 0) * 36 + bq * 4) = make_float4(a00.x, a00.y, a01.x, a01.y);
        *(float4*)(z_s + (2 * cp + 1) * 36 + bq * 4) = make_float4(a10.x, a10.y, a11.x, a11.y);
        __syncthreads();

        // ---- gate phase: thread = (unit gu, batches gb and gb+16) ----
#pragma unroll
        for (int rb = 0; rb < 2; ++rb) {
            int b = gb + rb * 16;
            float zi = z_s[(0 * 8 + gu) * 36 + b] + zxi[rb] + bi;
            float zj = z_s[(1 * 8 + gu) * 36 + b] + zxj[rb] + bj;
            float zf = z_s[(2 * 8 + gu) * 36 + b] + zxf[rb] + bf;
            float zo = z_s[(3 * 8 + gu) * 36 + b] + zxo[rb] + bo;

            float ig = 1.f / (1.f + expf(-zi));
            float fg = 1.f / (1.f + expf(-(zf + 1.0f)));   // forget bias 1.0
            float jt = tanhf(zj);
            float cn = fg * creg[rb] + ig * jt;
            float og = 1.f / (1.f + expf(-zo));
            float hn = og * tanhf(cn);
            creg[rb] = cn;

            hwrite[(u0 + gu) * BB + b] = hn;
            hist[(size_t)(b * TT + t) * HH + u0 + gu] = hn;
        }

        // ---- grid barrier (skip after final step) ----
        if (t < TT - 1) {
            __threadfence();       // all threads: order h writes before arrive
            __syncthreads();       // also guards z_s reuse
            if (tid == 0) {
                unsigned prev = atomicAdd(&g_bar_count, 1u);
                unsigned target = (unsigned)(t + 1);
                if (prev == NBLK - 1) {
                    atomicExch(&g_bar_count, 0u);
                    atomicAdd(&g_bar_phase, 1u);   // release
                } else {
                    unsigned ph;
                    do {
                        asm volatile("ld.global.acquire.gpu.u32 %0, [%1];"
                                     : "=r"(ph) : "l"(&g_bar_phase));
                        if (ph >= target) break;
                        __nanosleep(32);
                    } while (true);
                }
            }
            __syncthreads();
        } else {
            __syncthreads();       // z_s guard on last step (before layer end)
        }
    }
}

// ---------------- host orchestration ---------------------------------------
extern "C" void kernel_launch(void* const* d_in, const int* in_sizes, int n_in,
                              void* d_out, int out_size)
{
    const float *x = nullptr, *W1 = nullptr, *b1 = nullptr, *W2 = nullptr, *b2 = nullptr;
    for (int i = 0; i < n_in; i++) {
        int s = in_sizes[i];
        const float* p = (const float*)d_in[i];
        if (s == BB * TT * DD) x = p;
        else if (s == (DD + HH) * GN) W1 = p;
        else if (s == (HH + HH) * GN) W2 = p;
        else if (s == GN) { if (!b1) b1 = p; else b2 = p; }
    }
    float* out = (float*)d_out;

    float *zx, *h1;
    { void* p; cudaGetSymbolAddress(&p, g_zx); zx = (float*)p; }
    { void* p; cudaGetSymbolAddress(&p, g_h1); h1 = (float*)p; }

    const int SMEM_BYTES = (HH * 32 + 128 * 32 + 32 * 36) * 4;  // ~148.5 KB
    cudaFuncSetAttribute(lstm_persistent,
                         cudaFuncAttributeMaxDynamicSharedMemorySize, SMEM_BYTES);

    dim3 gemm_grid(GN / GM_BN, MM / GM_BM);   // (32, 64)

    // ---- Layer 1 ----
    sgemm_kernel<<<gemm_grid, 256>>>(x, W1, zx, MM, GN, DD);
    reset_kernel<<<(2 * HH * BB + 255) / 256, 256>>>();
    lstm_persistent<<<NBLK, PTH, SMEM_BYTES>>>(W1 + (size_t)DD * GN, zx, b1, h1);

    // ---- Layer 2 ----
    sgemm_kernel<<<gemm_grid, 256>>>(h1, W2, zx, MM, GN, HH);
    reset_kernel<<<(2 * HH * BB + 255) / 256, 256>>>();
    lstm_persistent<<<NBLK, PTH, SMEM_BYTES>>>(W2 + (size_t)HH * GN, zx, b2, out);
}